// round 1
// baseline (speedup 1.0000x reference)
#include <cuda_runtime.h>
#include <cstdint>

// Problem constants
#define BATCH 4
#define SEQ   4096
#define DM    1024      // d_model
#define DI    2048      // d_inner (channels)
#define DS    16        // d_state
#define NTAPS 32        // FIR truncation length: ||A||^32 ~ 1e-13 -> negligible

// Scratch (device globals: allocation-free rule)
__device__ float d_xp  [BATCH * DI * SEQ];   // x @ w_in + b_in, layout [B][C][S]
__device__ float d_g   [BATCH * DI * SEQ];   // sigmoid(x @ w_gate + b_gate), [B][C][S]
__device__ float d_yg  [BATCH * DI * SEQ];   // fir(xp) * g, [B][C][S]
__device__ float d_taps[DI * NTAPS];         // k_j[c] = C_c . A_c^j B_c

// ---------------------------------------------------------------------------
// f32x2 packed-FMA helpers (FFMA2: 2x FFMA throughput, only via PTX)
// ---------------------------------------------------------------------------
__device__ __forceinline__ unsigned long long splat2(float a) {
    unsigned long long r;
    asm("mov.b64 %0, {%1, %1};" : "=l"(r) : "r"(__float_as_uint(a)));
    return r;
}
__device__ __forceinline__ void ffma2(unsigned long long& d,
                                      unsigned long long a,
                                      unsigned long long b) {
    asm("fma.rn.f32x2 %0, %1, %2, %0;" : "+l"(d) : "l"(a), "l"(b));
}
__device__ __forceinline__ float lo32(unsigned long long v) {
    return __uint_as_float((unsigned int)v);
}
__device__ __forceinline__ float hi32(unsigned long long v) {
    return __uint_as_float((unsigned int)(v >> 32));
}

// ---------------------------------------------------------------------------
// Kernel 0: per-channel FIR taps  k[c][j] = C_c^T A_c^j B_c
// ---------------------------------------------------------------------------
__global__ __launch_bounds__(256) void taps_kernel(
    const float* __restrict__ A,      // [C][16][16], h_new[n] = sum_m A[c][n][m] h[m]
    const float* __restrict__ B_ssm,  // [C][16]
    const float* __restrict__ C_ssm)  // [C][16]
{
    int c = blockIdx.x * blockDim.x + threadIdx.x;
    if (c >= DI) return;
    const float* Ac = A + (size_t)c * DS * DS;
    float v[DS], Cv[DS];
#pragma unroll
    for (int n = 0; n < DS; n++) {
        v[n]  = B_ssm[c * DS + n];
        Cv[n] = C_ssm[c * DS + n];
    }
    for (int j = 0; j < NTAPS; j++) {
        float y = 0.f;
#pragma unroll
        for (int n = 0; n < DS; n++) y = fmaf(Cv[n], v[n], y);
        d_taps[c * NTAPS + j] = y;
        float w[DS];
#pragma unroll
        for (int n = 0; n < DS; n++) {
            float acc = 0.f;
#pragma unroll
            for (int m = 0; m < DS; m++) acc = fmaf(Ac[n * DS + m], v[m], acc);
            w[n] = acc;
        }
#pragma unroll
        for (int n = 0; n < DS; n++) v[n] = w[n];
    }
}

// ---------------------------------------------------------------------------
// Kernel 1: dual GEMM  xp = x@w_in + b_in ; g = sigmoid(x@w_gate + b_gate)
// Output transposed to [B][C][S] for coalesced FIR access.
// Tiles: 128x128x16, 256 threads, 8x8 microtile, f32x2 packed FMA.
// grid = (2*DI/128, BATCH*SEQ/128)
// ---------------------------------------------------------------------------
__global__ __launch_bounds__(256, 2) void gemm_in_gate(
    const float* __restrict__ x,
    const float* __restrict__ w_in,  const float* __restrict__ b_in,
    const float* __restrict__ w_gate, const float* __restrict__ b_gate)
{
    __shared__ float As[16][128];   // [k][m]
    __shared__ float Bs[16][128];   // [k][n]

    const int nb   = blockIdx.x;
    const int mb   = blockIdx.y;
    const int gate = (nb >= DI / 128);
    const float* __restrict__ W    = gate ? w_gate : w_in;
    const float* __restrict__ bias = gate ? b_gate : b_in;
    float* dst = gate ? d_g : d_xp;
    const int n0 = (nb & (DI / 128 - 1)) * 128;
    const int m0 = mb * 128;

    const int t  = threadIdx.x;
    const int tx = t & 15;          // n direction
    const int ty = t >> 4;          // m direction

    unsigned long long acc[8][4];
#pragma unroll
    for (int i = 0; i < 8; i++)
#pragma unroll
        for (int j = 0; j < 4; j++) acc[i][j] = 0ull;

    for (int k0 = 0; k0 < DM; k0 += 16) {
        float4 av[2], bv[2];
#pragma unroll
        for (int r = 0; r < 2; r++) {
            int e = t + r * 256;
            int m = e >> 2, kq = e & 3;                 // A: 128 rows x 4 float4
            av[r] = *(const float4*)(x + (size_t)(m0 + m) * DM + k0 + kq * 4);
            int kk = e >> 5, nq = e & 31;               // B: 16 rows x 32 float4
            bv[r] = *(const float4*)(W + (size_t)(k0 + kk) * DI + n0 + nq * 4);
        }
        __syncthreads();
#pragma unroll
        for (int r = 0; r < 2; r++) {
            int e = t + r * 256;
            int m = e >> 2, kq = e & 3;
            As[kq * 4 + 0][m] = av[r].x;
            As[kq * 4 + 1][m] = av[r].y;
            As[kq * 4 + 2][m] = av[r].z;
            As[kq * 4 + 3][m] = av[r].w;
            int kk = e >> 5, nq = e & 31;
            *(float4*)&Bs[kk][nq * 4] = bv[r];
        }
        __syncthreads();
#pragma unroll
        for (int kk = 0; kk < 16; kk++) {
            float4 a0 = *(const float4*)&As[kk][ty * 8];
            float4 a1 = *(const float4*)&As[kk][ty * 8 + 4];
            const ulonglong2* bp = (const ulonglong2*)&Bs[kk][tx * 8];
            ulonglong2 b01 = bp[0];
            ulonglong2 b23 = bp[1];
            float a[8] = {a0.x, a0.y, a0.z, a0.w, a1.x, a1.y, a1.z, a1.w};
#pragma unroll
            for (int i = 0; i < 8; i++) {
                unsigned long long a2 = splat2(a[i]);
                ffma2(acc[i][0], a2, b01.x);
                ffma2(acc[i][1], a2, b01.y);
                ffma2(acc[i][2], a2, b23.x);
                ffma2(acc[i][3], a2, b23.y);
            }
        }
        __syncthreads();
    }

    // Epilogue: add bias, (sigmoid), write transposed [B][C][S]
    float f[8][8];
#pragma unroll
    for (int i = 0; i < 8; i++)
#pragma unroll
        for (int j4 = 0; j4 < 4; j4++) {
            f[i][j4 * 2 + 0] = lo32(acc[i][j4]);
            f[i][j4 * 2 + 1] = hi32(acc[i][j4]);
        }

    const int mbase = m0 + ty * 8;
    const int bb    = mbase >> 12;          // / SEQ
    const int sbase = mbase & (SEQ - 1);
    float* outp = dst + (size_t)bb * DI * SEQ + sbase;
#pragma unroll
    for (int j = 0; j < 8; j++) {
        int n = n0 + tx * 8 + j;
        float bvz = bias[n];
        float v[8];
#pragma unroll
        for (int i = 0; i < 8; i++) {
            float u = f[i][j] + bvz;
            if (gate) u = 1.f / (1.f + __expf(-u));
            v[i] = u;
        }
        float* p = outp + (size_t)n * SEQ;
        *(float4*)(p)     = make_float4(v[0], v[1], v[2], v[3]);
        *(float4*)(p + 4) = make_float4(v[4], v[5], v[6], v[7]);
    }
}

// ---------------------------------------------------------------------------
// Kernel 2: depthwise causal FIR + gate:  yg[b][c][s] = g * sum_j k[c][j]*xp[b][c][s-j]
// grid = (SEQ/1024, DI, BATCH), 256 threads, 4 outputs/thread
// ---------------------------------------------------------------------------
__global__ __launch_bounds__(256) void fir_kernel()
{
    __shared__ float sx[NTAPS + 1024];
    __shared__ float sk[NTAPS];
    const int t = threadIdx.x;
    const int chunk = blockIdx.x;
    const int c     = blockIdx.y;
    const int b     = blockIdx.z;
    const size_t base = ((size_t)b * DI + c) * SEQ;
    const int s0 = chunk * 1024;

    for (int idx = t; idx < NTAPS + 1024; idx += 256) {
        int s = s0 - NTAPS + idx;
        sx[idx] = (s >= 0) ? d_xp[base + s] : 0.f;
    }
    if (t < NTAPS) sk[t] = d_taps[c * NTAPS + t];
    __syncthreads();

#pragma unroll
    for (int r = 0; r < 4; r++) {
        int pos = t + r * 256;
        float acc = 0.f;
#pragma unroll
        for (int j = 0; j < NTAPS; j++)
            acc = fmaf(sk[j], sx[NTAPS + pos - j], acc);
        float gv = d_g[base + s0 + pos];
        d_yg[base + s0 + pos] = acc * gv;
    }
}

// ---------------------------------------------------------------------------
// Kernel 3: out = yg^T @ w_out + b_out.  yg is [B][C][S] (so A-operand is
// K-major already). Tiles 128x128x16, same microkernel as gemm1.
// grid = (DM/128, BATCH*SEQ/128)
// ---------------------------------------------------------------------------
__global__ __launch_bounds__(256, 2) void gemm_out(
    const float* __restrict__ w_out, const float* __restrict__ b_out,
    float* __restrict__ out)
{
    __shared__ float As[16][128];   // [k=c][m=s]
    __shared__ float Bs[16][128];   // [k=c][n=d]

    const int n0 = blockIdx.x * 128;
    const int m0 = blockIdx.y * 128;
    const int bb = m0 >> 12;
    const int s0 = m0 & (SEQ - 1);
    const float* __restrict__ Abase = d_yg + (size_t)bb * DI * SEQ + s0;

    const int t  = threadIdx.x;
    const int tx = t & 15;
    const int ty = t >> 4;

    unsigned long long acc[8][4];
#pragma unroll
    for (int i = 0; i < 8; i++)
#pragma unroll
        for (int j = 0; j < 4; j++) acc[i][j] = 0ull;

    for (int k0 = 0; k0 < DI; k0 += 16) {
        float4 av[2], bv[2];
#pragma unroll
        for (int r = 0; r < 2; r++) {
            int e = t + r * 256;
            int kk = e >> 5, q = e & 31;    // 16 rows x 32 float4 for both tiles
            av[r] = *(const float4*)(Abase + (size_t)(k0 + kk) * SEQ + q * 4);
            bv[r] = *(const float4*)(w_out + (size_t)(k0 + kk) * DM + n0 + q * 4);
        }
        __syncthreads();
#pragma unroll
        for (int r = 0; r < 2; r++) {
            int e = t + r * 256;
            int kk = e >> 5, q = e & 31;
            *(float4*)&As[kk][q * 4] = av[r];
            *(float4*)&Bs[kk][q * 4] = bv[r];
        }
        __syncthreads();
#pragma unroll
        for (int kk = 0; kk < 16; kk++) {
            float4 a0 = *(const float4*)&As[kk][ty * 8];
            float4 a1 = *(const float4*)&As[kk][ty * 8 + 4];
            const ulonglong2* bp = (const ulonglong2*)&Bs[kk][tx * 8];
            ulonglong2 b01 = bp[0];
            ulonglong2 b23 = bp[1];
            float a[8] = {a0.x, a0.y, a0.z, a0.w, a1.x, a1.y, a1.z, a1.w};
#pragma unroll
            for (int i = 0; i < 8; i++) {
                unsigned long long a2 = splat2(a[i]);
                ffma2(acc[i][0], a2, b01.x);
                ffma2(acc[i][1], a2, b01.y);
                ffma2(acc[i][2], a2, b23.x);
                ffma2(acc[i][3], a2, b23.y);
            }
        }
        __syncthreads();
    }

    float f[8][8];
#pragma unroll
    for (int i = 0; i < 8; i++)
#pragma unroll
        for (int j4 = 0; j4 < 4; j4++) {
            f[i][j4 * 2 + 0] = lo32(acc[i][j4]);
            f[i][j4 * 2 + 1] = hi32(acc[i][j4]);
        }

    const int ncol = n0 + tx * 8;
    float bz[8];
#pragma unroll
    for (int j = 0; j < 8; j++) bz[j] = b_out[ncol + j];

#pragma unroll
    for (int i = 0; i < 8; i++) {
        int row = m0 + ty * 8 + i;
        float* p = out + (size_t)row * DM + ncol;
        *(float4*)(p)     = make_float4(f[i][0] + bz[0], f[i][1] + bz[1],
                                        f[i][2] + bz[2], f[i][3] + bz[3]);
        *(float4*)(p + 4) = make_float4(f[i][4] + bz[4], f[i][5] + bz[5],
                                        f[i][6] + bz[6], f[i][7] + bz[7]);
    }
}

// ---------------------------------------------------------------------------
extern "C" void kernel_launch(void* const* d_in, const int* in_sizes, int n_in,
                              void* d_out, int out_size)
{
    const float* x      = (const float*)d_in[0];
    const float* w_in   = (const float*)d_in[1];
    const float* b_in   = (const float*)d_in[2];
    const float* w_gate = (const float*)d_in[3];
    const float* b_gate = (const float*)d_in[4];
    const float* A      = (const float*)d_in[5];
    const float* B_ssm  = (const float*)d_in[6];
    const float* C_ssm  = (const float*)d_in[7];
    const float* w_out  = (const float*)d_in[8];
    const float* b_out  = (const float*)d_in[9];
    float* out = (float*)d_out;

    taps_kernel<<<DI / 256, 256>>>(A, B_ssm, C_ssm);
    gemm_in_gate<<<dim3(2 * DI / 128, BATCH * SEQ / 128), 256>>>(
        x, w_in, b_in, w_gate, b_gate);
    fir_kernel<<<dim3(SEQ / 1024, DI, BATCH), 256>>>();
    gemm_out<<<dim3(DM / 128, BATCH * SEQ / 128), 256>>>(w_out, b_out, out);
}

// round 4
// speedup vs baseline: 1.8356x; 1.8356x over previous
#include <cuda_runtime.h>
#include <cuda_bf16.h>
#include <cstdint>

// ---------------------------------------------------------------- constants
#define BATCH 4
#define SEQ   4096
#define DM    1024
#define DI    2048
#define DS    16
#define NTAPS 32

// ---------------------------------------------------------------- scratch (device globals)
__device__ float d_xp[BATCH*DI*SEQ];            // x@w_in+b (f32, [B][C][S])
__device__ float d_g [BATCH*DI*SEQ];            // sigmoid gate (f32, [B][C][S])
__device__ float d_yg[BATCH*DI*SEQ];            // fir*gate (f32, [B][C][S])
__device__ float d_taps[DI*NTAPS];
__device__ __nv_bfloat16 d_xs    [(size_t)BATCH*SEQ*2*DM];   // [16384][2048] = [hi|lo]
__device__ __nv_bfloat16 d_ys    [(size_t)BATCH*SEQ*2*DI];   // [16384][4096] = [hi|lo]
__device__ __nv_bfloat16 d_win_s [(size_t)DI*2*DM];          // [2048][2048] = [hi|lo]
__device__ __nv_bfloat16 d_wg_s  [(size_t)DI*2*DM];
__device__ __nv_bfloat16 d_wout_s[(size_t)DM*2*DI];          // [1024][4096] = [hi|lo]

// ---------------------------------------------------------------- utils
__device__ __forceinline__ uint32_t smem_u32(const void* p) {
    uint32_t a;
    asm("{ .reg .u64 t; cvta.to.shared.u64 t, %1; cvt.u32.u64 %0, t; }"
        : "=r"(a) : "l"(p));
    return a;
}
__device__ __forceinline__ void cpa16(uint32_t dst, const void* src) {
    asm volatile("cp.async.cg.shared.global [%0], [%1], 16;"
                 :: "r"(dst), "l"(src) : "memory");
}
#define CP_COMMIT() asm volatile("cp.async.commit_group;" ::: "memory")
template<int N> __device__ __forceinline__ void cp_wait() {
    asm volatile("cp.async.wait_group %0;" :: "n"(N) : "memory");
}
__device__ __forceinline__ void ldmx4(uint32_t* r, uint32_t addr) {
    asm volatile("ldmatrix.sync.aligned.m8n8.x4.shared.b16 {%0,%1,%2,%3}, [%4];"
                 : "=r"(r[0]), "=r"(r[1]), "=r"(r[2]), "=r"(r[3]) : "r"(addr));
}
__device__ __forceinline__ void mma16816(float* c, const uint32_t* a,
                                         uint32_t b0, uint32_t b1) {
    asm volatile(
        "mma.sync.aligned.m16n8k16.row.col.f32.bf16.bf16.f32 "
        "{%0,%1,%2,%3}, {%4,%5,%6,%7}, {%8,%9}, {%0,%1,%2,%3};"
        : "+f"(c[0]), "+f"(c[1]), "+f"(c[2]), "+f"(c[3])
        : "r"(a[0]), "r"(a[1]), "r"(a[2]), "r"(a[3]), "r"(b0), "r"(b1));
}
__device__ __forceinline__ void split1(float f, unsigned short& h, unsigned short& l) {
    __nv_bfloat16 hb = __float2bfloat16_rn(f);
    float r = f - __bfloat162float(hb);
    __nv_bfloat16 lb = __float2bfloat16_rn(r);
    h = reinterpret_cast<unsigned short&>(hb);
    l = reinterpret_cast<unsigned short&>(lb);
}

// ---------------------------------------------------------------- taps
__global__ __launch_bounds__(256) void taps_kernel(
    const float* __restrict__ A, const float* __restrict__ B_ssm,
    const float* __restrict__ C_ssm)
{
    int c = blockIdx.x * blockDim.x + threadIdx.x;
    if (c >= DI) return;
    const float* Ac = A + (size_t)c * DS * DS;
    float v[DS], Cv[DS];
#pragma unroll
    for (int n = 0; n < DS; n++) { v[n] = B_ssm[c*DS+n]; Cv[n] = C_ssm[c*DS+n]; }
    for (int j = 0; j < NTAPS; j++) {
        float y = 0.f;
#pragma unroll
        for (int n = 0; n < DS; n++) y = fmaf(Cv[n], v[n], y);
        d_taps[c*NTAPS + j] = y;
        float w[DS];
#pragma unroll
        for (int n = 0; n < DS; n++) {
            float acc = 0.f;
#pragma unroll
            for (int m = 0; m < DS; m++) acc = fmaf(Ac[n*DS+m], v[m], acc);
            w[n] = acc;
        }
#pragma unroll
        for (int n = 0; n < DS; n++) v[n] = w[n];
    }
}

// ---------------------------------------------------------------- split x: [M][K]f32 -> [M][2K]bf16
__global__ __launch_bounds__(256) void split_x_kernel(const float* __restrict__ x)
{
    int idx = blockIdx.x * 256 + threadIdx.x;
    int m  = idx >> 8;
    int kq = (idx & 255) * 4;
    float4 v = *(const float4*)(x + (size_t)m * DM + kq);
    ushort4 h, l;
    split1(v.x, h.x, l.x); split1(v.y, h.y, l.y);
    split1(v.z, h.z, l.z); split1(v.w, h.w, l.w);
    unsigned short* o = (unsigned short*)d_xs + (size_t)m * (2*DM) + kq;
    *(ushort4*)(o)      = h;
    *(ushort4*)(o + DM) = l;
}

// ---------------------------------------------------------------- split W: [K][N]f32 -> [N][2K]bf16
// WHICH: 0 -> d_win_s, 1 -> d_wg_s, 2 -> d_wout_s   (globals referenced from DEVICE code)
template<int WHICH, int K, int N>
__global__ void split_w_kernel(const float* __restrict__ W)
{
    __shared__ float tb[32][33];
    unsigned short* WT = (unsigned short*)(WHICH == 0 ? d_win_s
                                         : WHICH == 1 ? d_wg_s : d_wout_s);
    int n0 = blockIdx.x * 32, k0 = blockIdx.y * 32;
    int tx = threadIdx.x, ty = threadIdx.y;
#pragma unroll
    for (int i = ty; i < 32; i += 8)
        tb[i][tx] = W[(size_t)(k0 + i) * N + n0 + tx];
    __syncthreads();
#pragma unroll
    for (int j = ty; j < 32; j += 8) {
        float v = tb[tx][j];
        unsigned short h, l; split1(v, h, l);
        size_t rb = (size_t)(n0 + j) * (2 * K);
        WT[rb + k0 + tx]     = h;
        WT[rb + K + k0 + tx] = l;
    }
}

// ---------------------------------------------------------------- FIR + gate
__global__ __launch_bounds__(256) void fir_kernel()
{
    __shared__ float sx[NTAPS + 1024];
    __shared__ float sk[NTAPS];
    const int t = threadIdx.x;
    const int c = blockIdx.y, b = blockIdx.z;
    const size_t base = ((size_t)b * DI + c) * SEQ;
    const int s0 = blockIdx.x * 1024;

    for (int idx = t; idx < NTAPS + 1024; idx += 256) {
        int s = s0 - NTAPS + idx;
        sx[idx] = (s >= 0) ? d_xp[base + s] : 0.f;
    }
    if (t < NTAPS) sk[t] = d_taps[c * NTAPS + t];
    __syncthreads();
#pragma unroll
    for (int r = 0; r < 4; r++) {
        int pos = t + r * 256;
        float acc = 0.f;
#pragma unroll
        for (int j = 0; j < NTAPS; j++)
            acc = fmaf(sk[j], sx[NTAPS + pos - j], acc);
        d_yg[base + s0 + pos] = acc * d_g[base + s0 + pos];
    }
}

// ---------------------------------------------------------------- yg [B][C][S] -> d_ys [B*S][2*DI]
__global__ void trans_split_yg_kernel()
{
    __shared__ float tb[32][33];
    int s0 = blockIdx.x * 32, c0 = blockIdx.y * 32, b = blockIdx.z;
    int tx = threadIdx.x, ty = threadIdx.y;
    const float* src = d_yg + ((size_t)b * DI + c0) * SEQ + s0;
#pragma unroll
    for (int i = ty; i < 32; i += 8)
        tb[i][tx] = src[(size_t)i * SEQ + tx];
    __syncthreads();
    unsigned short* O = (unsigned short*)d_ys;
#pragma unroll
    for (int j = ty; j < 32; j += 8) {
        float v = tb[tx][j];
        unsigned short h, l; split1(v, h, l);
        size_t rb = ((size_t)b * SEQ + s0 + j) * (2 * DI);
        O[rb + c0 + tx]      = h;
        O[rb + DI + c0 + tx] = l;
    }
}

// ---------------------------------------------------------------- mma.sync GEMM
// C[128x128] per CTA. A [M][2K] bf16 ([hi|lo]), B [N][2K] bf16 ([hi|lo]).
// Split sum ah*bh + al*bh + ah*bl via 3 K-segments with pointer remap.
// BK=64 (128B rows, XOR-8 swizzle), 4-stage cp.async, 8 warps 64x32 tiles.
#define BKB        128                    // bytes per smem row (64 bf16)
#define STAGE_B    32768                  // 16KB A + 16KB B
#define NSTAGE     4
#define SMEM_GEMM  (NSTAGE * STAGE_B)

__device__ __forceinline__ void load_stage(uint32_t sb, int slot,
                                           const __nv_bfloat16* Ac,
                                           const __nv_bfloat16* Bc,
                                           int ldA, int ldB)
{
    uint32_t sA = sb + slot * STAGE_B;
    uint32_t sB = sA + 16384;
    const int t = threadIdx.x;
#pragma unroll
    for (int it = 0; it < 4; it++) {
        int idx = t + it * 256;
        int r = idx >> 3, c = idx & 7;
        cpa16(sA + r * BKB + ((c ^ (r & 7)) << 4),
              (const char*)Ac + (size_t)r * ldA + c * 16);
    }
#pragma unroll
    for (int it = 0; it < 4; it++) {
        int idx = t + it * 256;
        int r = idx >> 3, c = idx & 7;
        cpa16(sB + r * BKB + ((c ^ (r & 7)) << 4),
              (const char*)Bc + (size_t)r * ldB + c * 16);
    }
}

// EPI 0: A=d_xs, B=d_win_s/d_wg_s (dual), writes d_xp/d_g transposed.
// EPI 1: A=d_ys, B=d_wout_s, writes out rows.
template<int EPI, int KBASE>
__global__ __launch_bounds__(256) void gemm_mma(
    const float* __restrict__ bias0, const float* __restrict__ bias1,
    float* __restrict__ outp)
{
    extern __shared__ char smem[];
    uint32_t sb = smem_u32(smem);
    const int t   = threadIdx.x;
    const int wid = t >> 5, lid = t & 31;
    const int ldA = 2 * KBASE * 2;        // row stride in bytes
    const int NS  = KBASE / 64;           // chunks per segment
    const int NKC = 3 * NS;

    int sel, n0;
    const __nv_bfloat16* Aglob;
    const __nv_bfloat16* B;
    const float* bias;
    if (EPI == 0) {
        Aglob = d_xs;
        sel = (blockIdx.x >= DI / 128);
        n0  = (blockIdx.x & (DI / 128 - 1)) * 128;
        B = sel ? d_wg_s : d_win_s;
        bias = sel ? bias1 : bias0;
    } else {
        Aglob = d_ys;
        sel = 0;
        n0  = blockIdx.x * 128;
        B = d_wout_s;
        bias = bias0;
    }
    const int m0 = blockIdx.y * 128;
    const __nv_bfloat16* Abase = Aglob + (size_t)m0 * (2 * KBASE);
    const __nv_bfloat16* Bbase = B + (size_t)n0 * (2 * KBASE);

    // chunk -> element offset within the 2K row, for A and B
    auto a_off = [&](int i) {
        int seg = i / NS, off = i - seg * NS;
        return (seg == 1 ? KBASE : 0) + off * 64;   // seg0:hi seg1:lo seg2:hi
    };
    auto b_off = [&](int i) {
        int seg = i / NS, off = i - seg * NS;
        return (seg == 2 ? KBASE : 0) + off * 64;   // seg0:hi seg1:hi seg2:lo
    };

    // prologue
#pragma unroll
    for (int p = 0; p < NSTAGE - 1; p++) {
        load_stage(sb, p, Abase + a_off(p), Bbase + b_off(p), ldA, ldA);
        CP_COMMIT();
    }

    const int wm = (wid & 1) * 64;        // warp m-base within CTA
    const int wn = (wid >> 1) * 32;       // warp n-base

    float acc[4][4][4];
#pragma unroll
    for (int i = 0; i < 4; i++)
#pragma unroll
        for (int j = 0; j < 4; j++)
#pragma unroll
            for (int q = 0; q < 4; q++) acc[i][j][q] = 0.f;

    for (int i = 0; i < NKC; i++) {
        cp_wait<NSTAGE - 2>();
        __syncthreads();
        int j = i + NSTAGE - 1;
        if (j < NKC) {
            load_stage(sb, j & (NSTAGE - 1), Abase + a_off(j), Bbase + b_off(j),
                       ldA, ldA);
        }
        CP_COMMIT();

        uint32_t sA = sb + (i & (NSTAGE - 1)) * STAGE_B;
        uint32_t sB = sA + 16384;
#pragma unroll
        for (int kk = 0; kk < 4; kk++) {
            uint32_t a[4][4], b[2][4];
#pragma unroll
            for (int mi = 0; mi < 4; mi++) {
                int row = wm + mi * 16 + (lid & 15);
                int ch  = kk * 2 + (lid >> 4);
                ldmx4(a[mi], sA + row * BKB + ((ch ^ (row & 7)) << 4));
            }
#pragma unroll
            for (int bi = 0; bi < 2; bi++) {
                int row = wn + bi * 16 + (lid & 15);
                int ch  = kk * 2 + (lid >> 4);
                ldmx4(b[bi], sB + row * BKB + ((ch ^ (row & 7)) << 4));
            }
#pragma unroll
            for (int mi = 0; mi < 4; mi++) {
#pragma unroll
                for (int bi = 0; bi < 2; bi++) {
                    mma16816(acc[mi][bi * 2 + 0], a[mi], b[bi][0], b[bi][2]);
                    mma16816(acc[mi][bi * 2 + 1], a[mi], b[bi][1], b[bi][3]);
                }
            }
        }
        __syncthreads();
    }

    // ---- epilogue ----
    const int bidx = m0 >> 12;            // batch (constant per CTA)
    const int q4   = lid & 3;
    const int r8   = lid >> 2;

    if (EPI == 0) {
        float* dp = (sel ? d_g : d_xp) + (size_t)bidx * DI * SEQ;
#pragma unroll
        for (int mi = 0; mi < 4; mi++) {
#pragma unroll
            for (int ni = 0; ni < 4; ni++) {
                int n = n0 + wn + ni * 8 + 2 * q4;
                float bz0 = bias[n], bz1 = bias[n + 1];
#pragma unroll
                for (int rr = 0; rr < 2; rr++) {
                    int m = m0 + wm + mi * 16 + r8 + rr * 8;
                    int s = m & (SEQ - 1);
                    float v0 = acc[mi][ni][rr * 2 + 0] + bz0;
                    float v1 = acc[mi][ni][rr * 2 + 1] + bz1;
                    if (sel) {
                        v0 = 1.f / (1.f + __expf(-v0));
                        v1 = 1.f / (1.f + __expf(-v1));
                    }
                    dp[(size_t)n * SEQ + s]       = v0;
                    dp[(size_t)(n + 1) * SEQ + s] = v1;
                }
            }
        }
    } else {
#pragma unroll
        for (int mi = 0; mi < 4; mi++) {
#pragma unroll
            for (int ni = 0; ni < 4; ni++) {
                int n = n0 + wn + ni * 8 + 2 * q4;
                float bz0 = bias[n], bz1 = bias[n + 1];
#pragma unroll
                for (int rr = 0; rr < 2; rr++) {
                    int m = m0 + wm + mi * 16 + r8 + rr * 8;
                    float2 v;
                    v.x = acc[mi][ni][rr * 2 + 0] + bz0;
                    v.y = acc[mi][ni][rr * 2 + 1] + bz1;
                    *(float2*)(outp + (size_t)m * DM + n) = v;
                }
            }
        }
    }
}

// ---------------------------------------------------------------- launch
extern "C" void kernel_launch(void* const* d_in, const int* in_sizes, int n_in,
                              void* d_out, int out_size)
{
    const float* x      = (const float*)d_in[0];
    const float* w_in   = (const float*)d_in[1];
    const float* b_in   = (const float*)d_in[2];
    const float* w_gate = (const float*)d_in[3];
    const float* b_gate = (const float*)d_in[4];
    const float* A      = (const float*)d_in[5];
    const float* B_ssm  = (const float*)d_in[6];
    const float* C_ssm  = (const float*)d_in[7];
    const float* w_out  = (const float*)d_in[8];
    const float* b_out  = (const float*)d_in[9];
    float* out = (float*)d_out;

    static bool attr_done = false;
    if (!attr_done) {
        cudaFuncSetAttribute(gemm_mma<0, DM>,
                             cudaFuncAttributeMaxDynamicSharedMemorySize, SMEM_GEMM);
        cudaFuncSetAttribute(gemm_mma<1, DI>,
                             cudaFuncAttributeMaxDynamicSharedMemorySize, SMEM_GEMM);
        attr_done = true;
    }

    taps_kernel<<<DI / 256, 256>>>(A, B_ssm, C_ssm);
    split_x_kernel<<<(BATCH * SEQ * DM / 4) / 256, 256>>>(x);
    split_w_kernel<0, DM, DI><<<dim3(DI / 32, DM / 32), dim3(32, 8)>>>(w_in);
    split_w_kernel<1, DM, DI><<<dim3(DI / 32, DM / 32), dim3(32, 8)>>>(w_gate);
    split_w_kernel<2, DI, DM><<<dim3(DM / 32, DI / 32), dim3(32, 8)>>>(w_out);

    gemm_mma<0, DM><<<dim3(2 * DI / 128, BATCH * SEQ / 128), 256, SMEM_GEMM>>>(
        b_in, b_gate, nullptr);

    fir_kernel<<<dim3(SEQ / 1024, DI, BATCH), 256>>>();
    trans_split_yg_kernel<<<dim3(SEQ / 32, DI / 32, BATCH), dim3(32, 8)>>>();

    gemm_mma<1, DI><<<dim3(DM / 128, BATCH * SEQ / 128), 256, SMEM_GEMM>>>(
        b_out, nullptr, out);
}

// round 5
// speedup vs baseline: 2.8541x; 1.5548x over previous
#include <cuda_runtime.h>
#include <cuda_fp16.h>
#include <cstdint>

// ---------------------------------------------------------------- constants
#define BATCH 4
#define SEQ   4096
#define DM    1024
#define DI    2048
#define DS    16
#define NTAPS 32

// ---------------------------------------------------------------- scratch (device globals)
__device__ float d_xp[BATCH*DI*SEQ];            // x@w_in+b (f32, [B][C][S])
__device__ float d_g [BATCH*DI*SEQ];            // sigmoid gate (f32, [B][C][S])
__device__ float d_yg[BATCH*DI*SEQ];            // fir*gate (f32, [B][C][S])
__device__ float d_taps[DI*NTAPS];
__device__ __half d_xh    [(size_t)BATCH*SEQ*DM];    // [16384][1024] fp16 activations
__device__ __half d_yh    [(size_t)BATCH*SEQ*DI];    // [16384][2048] fp16 activations
__device__ __half d_win_s [(size_t)DI*2*DM];         // [2048][2048] = [hi|lo]
__device__ __half d_wg_s  [(size_t)DI*2*DM];
__device__ __half d_wout_s[(size_t)DM*2*DI];         // [1024][4096] = [hi|lo]

// ---------------------------------------------------------------- utils
__device__ __forceinline__ uint32_t smem_u32(const void* p) {
    uint32_t a;
    asm("{ .reg .u64 t; cvta.to.shared.u64 t, %1; cvt.u32.u64 %0, t; }"
        : "=r"(a) : "l"(p));
    return a;
}
__device__ __forceinline__ void cpa16(uint32_t dst, const void* src) {
    asm volatile("cp.async.cg.shared.global [%0], [%1], 16;"
                 :: "r"(dst), "l"(src) : "memory");
}
#define CP_COMMIT() asm volatile("cp.async.commit_group;" ::: "memory")
template<int N> __device__ __forceinline__ void cp_wait() {
    asm volatile("cp.async.wait_group %0;" :: "n"(N) : "memory");
}
__device__ __forceinline__ void ldmx4(uint32_t* r, uint32_t addr) {
    asm volatile("ldmatrix.sync.aligned.m8n8.x4.shared.b16 {%0,%1,%2,%3}, [%4];"
                 : "=r"(r[0]), "=r"(r[1]), "=r"(r[2]), "=r"(r[3]) : "r"(addr));
}
__device__ __forceinline__ void mma16816(float* c, const uint32_t* a,
                                         uint32_t b0, uint32_t b1) {
    asm volatile(
        "mma.sync.aligned.m16n8k16.row.col.f32.f16.f16.f32 "
        "{%0,%1,%2,%3}, {%4,%5,%6,%7}, {%8,%9}, {%0,%1,%2,%3};"
        : "+f"(c[0]), "+f"(c[1]), "+f"(c[2]), "+f"(c[3])
        : "r"(a[0]), "r"(a[1]), "r"(a[2]), "r"(a[3]), "r"(b0), "r"(b1));
}
__device__ __forceinline__ void splitw(float f, unsigned short& h, unsigned short& l) {
    __half hh = __float2half_rn(f);
    __half hl = __float2half_rn(f - __half2float(hh));
    h = reinterpret_cast<unsigned short&>(hh);
    l = reinterpret_cast<unsigned short&>(hl);
}

// ---------------------------------------------------------------- taps
__global__ __launch_bounds__(256) void taps_kernel(
    const float* __restrict__ A, const float* __restrict__ B_ssm,
    const float* __restrict__ C_ssm)
{
    int c = blockIdx.x * blockDim.x + threadIdx.x;
    if (c >= DI) return;
    const float* Ac = A + (size_t)c * DS * DS;
    float v[DS], Cv[DS];
#pragma unroll
    for (int n = 0; n < DS; n++) { v[n] = B_ssm[c*DS+n]; Cv[n] = C_ssm[c*DS+n]; }
    for (int j = 0; j < NTAPS; j++) {
        float y = 0.f;
#pragma unroll
        for (int n = 0; n < DS; n++) y = fmaf(Cv[n], v[n], y);
        d_taps[c*NTAPS + j] = y;
        float w[DS];
#pragma unroll
        for (int n = 0; n < DS; n++) {
            float acc = 0.f;
#pragma unroll
            for (int m = 0; m < DS; m++) acc = fmaf(Ac[n*DS+m], v[m], acc);
            w[n] = acc;
        }
#pragma unroll
        for (int n = 0; n < DS; n++) v[n] = w[n];
    }
}

// ---------------------------------------------------------------- x f32 -> fp16
__global__ __launch_bounds__(256) void conv_x_kernel(const float* __restrict__ x)
{
    size_t idx = (size_t)blockIdx.x * 256 + threadIdx.x;   // one float4
    float4 v = *(const float4*)(x + idx * 4);
    __half h[4] = { __float2half_rn(v.x), __float2half_rn(v.y),
                    __float2half_rn(v.z), __float2half_rn(v.w) };
    *(uint2*)((__half*)d_xh + idx * 4) = *(uint2*)h;
}

// ---------------------------------------------------------------- split W: [K][N]f32 -> [N][2K]fp16 [hi|lo]
template<int WHICH, int K, int N>
__global__ void split_w_kernel(const float* __restrict__ W)
{
    __shared__ float tb[32][33];
    unsigned short* WT = (unsigned short*)(WHICH == 0 ? d_win_s
                                         : WHICH == 1 ? d_wg_s : d_wout_s);
    int n0 = blockIdx.x * 32, k0 = blockIdx.y * 32;
    int tx = threadIdx.x, ty = threadIdx.y;
#pragma unroll
    for (int i = ty; i < 32; i += 8)
        tb[i][tx] = W[(size_t)(k0 + i) * N + n0 + tx];
    __syncthreads();
#pragma unroll
    for (int j = ty; j < 32; j += 8) {
        float v = tb[tx][j];
        unsigned short h, l; splitw(v, h, l);
        size_t rb = (size_t)(n0 + j) * (2 * K);
        WT[rb + k0 + tx]     = h;
        WT[rb + K + k0 + tx] = l;
    }
}

// ---------------------------------------------------------------- FIR + gate
__global__ __launch_bounds__(256) void fir_kernel()
{
    __shared__ float sx[NTAPS + 1024];
    __shared__ float sk[NTAPS];
    const int t = threadIdx.x;
    const int c = blockIdx.y, b = blockIdx.z;
    const size_t base = ((size_t)b * DI + c) * SEQ;
    const int s0 = blockIdx.x * 1024;

    for (int idx = t; idx < NTAPS + 1024; idx += 256) {
        int s = s0 - NTAPS + idx;
        sx[idx] = (s >= 0) ? d_xp[base + s] : 0.f;
    }
    if (t < NTAPS) sk[t] = d_taps[c * NTAPS + t];
    __syncthreads();
#pragma unroll
    for (int r = 0; r < 4; r++) {
        int pos = t + r * 256;
        float acc = 0.f;
#pragma unroll
        for (int j = 0; j < NTAPS; j++)
            acc = fmaf(sk[j], sx[NTAPS + pos - j], acc);
        d_yg[base + s0 + pos] = acc * d_g[base + s0 + pos];
    }
}

// ---------------------------------------------------------------- yg [B][C][S]f32 -> d_yh [B*S][DI]fp16
__global__ void trans_yg_kernel()
{
    __shared__ float tb[32][33];
    int s0 = blockIdx.x * 32, c0 = blockIdx.y * 32, b = blockIdx.z;
    int tx = threadIdx.x, ty = threadIdx.y;
    const float* src = d_yg + ((size_t)b * DI + c0) * SEQ + s0;
#pragma unroll
    for (int i = ty; i < 32; i += 8)
        tb[i][tx] = src[(size_t)i * SEQ + tx];
    __syncthreads();
    __half* O = (__half*)d_yh;
#pragma unroll
    for (int j = ty; j < 32; j += 8)
        O[((size_t)b * SEQ + s0 + j) * DI + c0 + tx] = __float2half_rn(tb[tx][j]);
}

// ---------------------------------------------------------------- mma.sync GEMM (fp16, weight 2-seg split)
// C[128x128] per CTA. A [M][K] fp16. B [N][2K] fp16 ([hi|lo]).
// Per K-chunk: load A once + both B segments; accumulate a*bh + a*bl into same acc.
// BK=64 (128B rows, XOR-8 swizzle), 4-stage cp.async, 8 warps 64x32 tiles.
#define BKB        128                    // bytes per smem row (64 fp16)
#define STAGE_B    49152                  // 16KB A + 32KB B (2 segments)
#define NSTAGE     4
#define SMEM_GEMM  (NSTAGE * STAGE_B)

template<int KBASE>
__device__ __forceinline__ void load_stage(uint32_t sb, int slot,
                                           const char* Ac, const char* Bc)
{
    const int ldA = KBASE * 2;            // A row stride bytes
    const int ldB = 2 * KBASE * 2;        // B row stride bytes
    uint32_t sA = sb + slot * STAGE_B;
    uint32_t sB = sA + 16384;
    const int t = threadIdx.x;
#pragma unroll
    for (int it = 0; it < 4; it++) {
        int idx = t + it * 256;
        int r = idx >> 3, c = idx & 7;
        cpa16(sA + r * BKB + ((c ^ (r & 7)) << 4), Ac + (size_t)r * ldA + c * 16);
    }
#pragma unroll
    for (int it = 0; it < 8; it++) {
        int idx = t + it * 256;           // 0..2047
        int seg = idx >> 10;
        int r = (idx >> 3) & 127, c = idx & 7;
        cpa16(sB + seg * 16384 + r * BKB + ((c ^ (r & 7)) << 4),
              Bc + (size_t)r * ldB + seg * (KBASE * 2) + c * 16);
    }
}

// EPI 0: A=d_xh, B=d_win_s/d_wg_s (dual), writes d_xp/d_g transposed.
// EPI 1: A=d_yh, B=d_wout_s, writes out rows.
template<int EPI, int KBASE>
__global__ __launch_bounds__(256) void gemm_mma(
    const float* __restrict__ bias0, const float* __restrict__ bias1,
    float* __restrict__ outp)
{
    extern __shared__ char smem[];
    uint32_t sb = smem_u32(smem);
    const int t   = threadIdx.x;
    const int wid = t >> 5, lid = t & 31;
    const int NKC = KBASE / 64;           // K-chunks

    int sel, n0;
    const __half* Aglob;
    const __half* B;
    const float* bias;
    if (EPI == 0) {
        Aglob = d_xh;
        sel = (blockIdx.x >= DI / 128);
        n0  = (blockIdx.x & (DI / 128 - 1)) * 128;
        B = sel ? d_wg_s : d_win_s;
        bias = sel ? bias1 : bias0;
    } else {
        Aglob = d_yh;
        sel = 0;
        n0  = blockIdx.x * 128;
        B = d_wout_s;
        bias = bias0;
    }
    const int m0 = blockIdx.y * 128;
    const char* Abase = (const char*)(Aglob + (size_t)m0 * KBASE);
    const char* Bbase = (const char*)(B + (size_t)n0 * (2 * KBASE));

    // prologue
#pragma unroll
    for (int p = 0; p < NSTAGE - 1; p++) {
        load_stage<KBASE>(sb, p, Abase + p * 128, Bbase + p * 128);
        CP_COMMIT();
    }

    const int wm = (wid & 1) * 64;        // warp m-base
    const int wn = (wid >> 1) * 32;       // warp n-base

    float acc[4][4][4];
#pragma unroll
    for (int i = 0; i < 4; i++)
#pragma unroll
        for (int j = 0; j < 4; j++)
#pragma unroll
            for (int q = 0; q < 4; q++) acc[i][j][q] = 0.f;

    for (int i = 0; i < NKC; i++) {
        cp_wait<NSTAGE - 2>();
        __syncthreads();
        int j = i + NSTAGE - 1;
        if (j < NKC) {
            load_stage<KBASE>(sb, j & (NSTAGE - 1), Abase + j * 128,
                              Bbase + j * 128);
        }
        CP_COMMIT();

        uint32_t sA = sb + (i & (NSTAGE - 1)) * STAGE_B;
        uint32_t sB = sA + 16384;
#pragma unroll
        for (int kk = 0; kk < 4; kk++) {
            uint32_t a[4][4], b[2][2][4];
#pragma unroll
            for (int mi = 0; mi < 4; mi++) {
                int row = wm + mi * 16 + (lid & 15);
                int ch  = kk * 2 + (lid >> 4);
                ldmx4(a[mi], sA + row * BKB + ((ch ^ (row & 7)) << 4));
            }
#pragma unroll
            for (int seg = 0; seg < 2; seg++) {
#pragma unroll
                for (int bi = 0; bi < 2; bi++) {
                    int row = wn + bi * 16 + (lid & 15);
                    int ch  = kk * 2 + (lid >> 4);
                    ldmx4(b[seg][bi],
                          sB + seg * 16384 + row * BKB + ((ch ^ (row & 7)) << 4));
                }
            }
#pragma unroll
            for (int mi = 0; mi < 4; mi++) {
#pragma unroll
                for (int seg = 0; seg < 2; seg++) {
#pragma unroll
                    for (int bi = 0; bi < 2; bi++) {
                        mma16816(acc[mi][bi * 2 + 0], a[mi],
                                 b[seg][bi][0], b[seg][bi][2]);
                        mma16816(acc[mi][bi * 2 + 1], a[mi],
                                 b[seg][bi][1], b[seg][bi][3]);
                    }
                }
            }
        }
        __syncthreads();
    }

    // ---- epilogue ----
    const int bidx = m0 >> 12;            // batch (constant per CTA)
    const int q4   = lid & 3;
    const int r8   = lid >> 2;

    if (EPI == 0) {
        float* dp = (sel ? d_g : d_xp) + (size_t)bidx * DI * SEQ;
#pragma unroll
        for (int mi = 0; mi < 4; mi++) {
#pragma unroll
            for (int ni = 0; ni < 4; ni++) {
                int n = n0 + wn + ni * 8 + 2 * q4;
                float bz0 = bias[n], bz1 = bias[n + 1];
#pragma unroll
                for (int rr = 0; rr < 2; rr++) {
                    int m = m0 + wm + mi * 16 + r8 + rr * 8;
                    int s = m & (SEQ - 1);
                    float v0 = acc[mi][ni][rr * 2 + 0] + bz0;
                    float v1 = acc[mi][ni][rr * 2 + 1] + bz1;
                    if (sel) {
                        v0 = 1.f / (1.f + __expf(-v0));
                        v1 = 1.f / (1.f + __expf(-v1));
                    }
                    dp[(size_t)n * SEQ + s]       = v0;
                    dp[(size_t)(n + 1) * SEQ + s] = v1;
                }
            }
        }
    } else {
#pragma unroll
        for (int mi = 0; mi < 4; mi++) {
#pragma unroll
            for (int ni = 0; ni < 4; ni++) {
                int n = n0 + wn + ni * 8 + 2 * q4;
                float bz0 = bias[n], bz1 = bias[n + 1];
#pragma unroll
                for (int rr = 0; rr < 2; rr++) {
                    int m = m0 + wm + mi * 16 + r8 + rr * 8;
                    float2 v;
                    v.x = acc[mi][ni][rr * 2 + 0] + bz0;
                    v.y = acc[mi][ni][rr * 2 + 1] + bz1;
                    *(float2*)(outp + (size_t)m * DM + n) = v;
                }
            }
        }
    }
}

// ---------------------------------------------------------------- launch
extern "C" void kernel_launch(void* const* d_in, const int* in_sizes, int n_in,
                              void* d_out, int out_size)
{
    const float* x      = (const float*)d_in[0];
    const float* w_in   = (const float*)d_in[1];
    const float* b_in   = (const float*)d_in[2];
    const float* w_gate = (const float*)d_in[3];
    const float* b_gate = (const float*)d_in[4];
    const float* A      = (const float*)d_in[5];
    const float* B_ssm  = (const float*)d_in[6];
    const float* C_ssm  = (const float*)d_in[7];
    const float* w_out  = (const float*)d_in[8];
    const float* b_out  = (const float*)d_in[9];
    float* out = (float*)d_out;

    static bool attr_done = false;
    if (!attr_done) {
        cudaFuncSetAttribute(gemm_mma<0, DM>,
                             cudaFuncAttributeMaxDynamicSharedMemorySize, SMEM_GEMM);
        cudaFuncSetAttribute(gemm_mma<1, DI>,
                             cudaFuncAttributeMaxDynamicSharedMemorySize, SMEM_GEMM);
        attr_done = true;
    }

    taps_kernel<<<DI / 256, 256>>>(A, B_ssm, C_ssm);
    conv_x_kernel<<<(BATCH * SEQ * DM / 4) / 256, 256>>>(x);
    split_w_kernel<0, DM, DI><<<dim3(DI / 32, DM / 32), dim3(32, 8)>>>(w_in);
    split_w_kernel<1, DM, DI><<<dim3(DI / 32, DM / 32), dim3(32, 8)>>>(w_gate);
    split_w_kernel<2, DI, DM><<<dim3(DM / 32, DI / 32), dim3(32, 8)>>>(w_out);

    gemm_mma<0, DM><<<dim3(2 * DI / 128, BATCH * SEQ / 128), 256, SMEM_GEMM>>>(
        b_in, b_gate, nullptr);

    fir_kernel<<<dim3(SEQ / 1024, DI, BATCH), 256>>>();
    trans_yg_kernel<<<dim3(SEQ / 32, DI / 32, BATCH), dim3(32, 8)>>>();

    gemm_mma<1, DI><<<dim3(DM / 128, BATCH * SEQ / 128), 256, SMEM_GEMM>>>(
        b_out, nullptr, out);
}

// round 6
// speedup vs baseline: 4.2499x; 1.4891x over previous
#include <cuda_runtime.h>
#include <cuda_fp16.h>
#include <cstdint>

// ---------------------------------------------------------------- constants
#define BATCH 4
#define SEQ   4096
#define DM    1024
#define DI    2048
#define DS    16
#define NTAPS 32

// ---------------------------------------------------------------- scratch (device globals)
__device__ float d_xp[BATCH*DI*SEQ];            // x@w_in+b (f32, [B][C][S])
__device__ float d_g [(size_t)BATCH*SEQ*DI];    // sigmoid gate (f32, [B*S][C])
__device__ float d_taps[DI*NTAPS];
__device__ __half d_xh    [(size_t)BATCH*SEQ*DM];    // [16384][1024] fp16
__device__ __half d_yh    [(size_t)BATCH*SEQ*DI];    // [16384][2048] fp16 (fir*gate)
__device__ __half d_win_h [(size_t)DI*DM];           // [N][K]
__device__ __half d_wg_h  [(size_t)DI*DM];
__device__ __half d_wout_h[(size_t)DM*DI];           // [N][K]

// ---------------------------------------------------------------- utils
__device__ __forceinline__ uint32_t smem_u32(const void* p) {
    uint32_t a;
    asm("{ .reg .u64 t; cvta.to.shared.u64 t, %1; cvt.u32.u64 %0, t; }"
        : "=r"(a) : "l"(p));
    return a;
}
__device__ __forceinline__ void cpa16(uint32_t dst, const void* src) {
    asm volatile("cp.async.cg.shared.global [%0], [%1], 16;"
                 :: "r"(dst), "l"(src) : "memory");
}
#define CP_COMMIT() asm volatile("cp.async.commit_group;" ::: "memory")
template<int N> __device__ __forceinline__ void cp_wait() {
    asm volatile("cp.async.wait_group %0;" :: "n"(N) : "memory");
}
__device__ __forceinline__ void ldmx4(uint32_t* r, uint32_t addr) {
    asm volatile("ldmatrix.sync.aligned.m8n8.x4.shared.b16 {%0,%1,%2,%3}, [%4];"
                 : "=r"(r[0]), "=r"(r[1]), "=r"(r[2]), "=r"(r[3]) : "r"(addr));
}
__device__ __forceinline__ void mma16816(float* c, const uint32_t* a,
                                         uint32_t b0, uint32_t b1) {
    asm volatile(
        "mma.sync.aligned.m16n8k16.row.col.f32.f16.f16.f32 "
        "{%0,%1,%2,%3}, {%4,%5,%6,%7}, {%8,%9}, {%0,%1,%2,%3};"
        : "+f"(c[0]), "+f"(c[1]), "+f"(c[2]), "+f"(c[3])
        : "r"(a[0]), "r"(a[1]), "r"(a[2]), "r"(a[3]), "r"(b0), "r"(b1));
}

// ---------------------------------------------------------------- taps
__global__ __launch_bounds__(256) void taps_kernel(
    const float* __restrict__ A, const float* __restrict__ B_ssm,
    const float* __restrict__ C_ssm)
{
    int c = blockIdx.x * blockDim.x + threadIdx.x;
    if (c >= DI) return;
    const float* Ac = A + (size_t)c * DS * DS;
    float v[DS], Cv[DS];
#pragma unroll
    for (int n = 0; n < DS; n++) { v[n] = B_ssm[c*DS+n]; Cv[n] = C_ssm[c*DS+n]; }
    for (int j = 0; j < NTAPS; j++) {
        float y = 0.f;
#pragma unroll
        for (int n = 0; n < DS; n++) y = fmaf(Cv[n], v[n], y);
        d_taps[c*NTAPS + j] = y;
        float w[DS];
#pragma unroll
        for (int n = 0; n < DS; n++) {
            float acc = 0.f;
#pragma unroll
            for (int m = 0; m < DS; m++) acc = fmaf(Ac[n*DS+m], v[m], acc);
            w[n] = acc;
        }
#pragma unroll
        for (int n = 0; n < DS; n++) v[n] = w[n];
    }
}

// ---------------------------------------------------------------- x f32 -> fp16
__global__ __launch_bounds__(256) void conv_x_kernel(const float* __restrict__ x)
{
    size_t idx = (size_t)blockIdx.x * 256 + threadIdx.x;   // one float4
    float4 v = *(const float4*)(x + idx * 4);
    __half h[4] = { __float2half_rn(v.x), __float2half_rn(v.y),
                    __float2half_rn(v.z), __float2half_rn(v.w) };
    *(uint2*)((__half*)d_xh + idx * 4) = *(uint2*)h;
}

// ---------------------------------------------------------------- W [K][N]f32 -> [N][K]fp16
template<int WHICH, int K, int N>
__global__ void conv_w_kernel(const float* __restrict__ W)
{
    __shared__ float tb[32][33];
    __half* WT = (WHICH == 0 ? d_win_h : WHICH == 1 ? d_wg_h : d_wout_h);
    int n0 = blockIdx.x * 32, k0 = blockIdx.y * 32;
    int tx = threadIdx.x, ty = threadIdx.y;
#pragma unroll
    for (int i = ty; i < 32; i += 8)
        tb[i][tx] = W[(size_t)(k0 + i) * N + n0 + tx];
    __syncthreads();
#pragma unroll
    for (int j = ty; j < 32; j += 8)
        WT[(size_t)(n0 + j) * K + k0 + tx] = __float2half_rn(tb[tx][j]);
}

// ---------------------------------------------------------------- FIR + gate + fp16 transpose-store
// Block: 32 channels x 256 s. Thread t: c = t&31, 32 outputs (4 chunks of 8).
// Writes d_yh[(b*SEQ+s)*DI + c] directly (warp-coalesced 64B rows).
__global__ __launch_bounds__(256) void fir_kernel()
{
    __shared__ float sx[32][289];       // [c][32 halo + 256 + pad]
    __shared__ float st[32][33];        // taps
    const int t = threadIdx.x;
    const int c0 = blockIdx.y * 32, b = blockIdx.z;
    const int s0 = blockIdx.x * 256;

    for (int idx = t; idx < 32 * 288; idx += 256) {
        int r = idx / 288, z = idx % 288;
        int s = s0 - 32 + z;
        sx[r][z] = (s >= 0) ? d_xp[((size_t)b * DI + c0 + r) * SEQ + s] : 0.f;
    }
    for (int idx = t; idx < 32 * 32; idx += 256) {
        int r = idx >> 5, j = idx & 31;
        st[r][j] = d_taps[(c0 + r) * NTAPS + j];
    }
    __syncthreads();

    const int c  = t & 31;
    const int sb = (t >> 5) * 32;       // warp-uniform
    float k[NTAPS];
#pragma unroll
    for (int j = 0; j < NTAPS; j++) k[j] = st[c][j];

#pragma unroll
    for (int ch = 0; ch < 4; ch++) {
        const int sc = sb + ch * 8;
        float w[39];
#pragma unroll
        for (int z = 0; z < 39; z++) w[z] = sx[c][sc + 1 + z];
        float acc[8];
#pragma unroll
        for (int i = 0; i < 8; i++) acc[i] = 0.f;
#pragma unroll
        for (int j = 0; j < NTAPS; j++)
#pragma unroll
            for (int i = 0; i < 8; i++)
                acc[i] = fmaf(k[j], w[31 + i - j], acc[i]);
#pragma unroll
        for (int i = 0; i < 8; i++) {
            size_t row = (size_t)b * SEQ + s0 + sc + i;
            float gv = d_g[row * DI + c0 + c];
            d_yh[row * DI + c0 + c] = __float2half_rn(acc[i] * gv);
        }
    }
}

// ---------------------------------------------------------------- mma.sync GEMM (plain fp16)
// C[128x128] per CTA. A [M][K] fp16, B [N][K] fp16.
// BK=64 (128B rows, XOR-8 swizzle), 4-stage cp.async, 8 warps 64x32 tiles.
#define BKB        128                    // bytes per smem row (64 fp16)
#define STAGE_B    32768                  // 16KB A + 16KB B
#define NSTAGE     4
#define SMEM_GEMM  (NSTAGE * STAGE_B)

template<int KBASE>
__device__ __forceinline__ void load_stage(uint32_t sb, int slot,
                                           const char* Ac, const char* Bc)
{
    const int ld = KBASE * 2;             // row stride bytes (A and B identical)
    uint32_t sA = sb + slot * STAGE_B;
    uint32_t sB = sA + 16384;
    const int t = threadIdx.x;
#pragma unroll
    for (int it = 0; it < 4; it++) {
        int idx = t + it * 256;
        int r = idx >> 3, c = idx & 7;
        cpa16(sA + r * BKB + ((c ^ (r & 7)) << 4), Ac + (size_t)r * ld + c * 16);
    }
#pragma unroll
    for (int it = 0; it < 4; it++) {
        int idx = t + it * 256;
        int r = idx >> 3, c = idx & 7;
        cpa16(sB + r * BKB + ((c ^ (r & 7)) << 4), Bc + (size_t)r * ld + c * 16);
    }
}

// EPI 0: A=d_xh, B=d_win_h/d_wg_h (dual), writes d_xp ([C][S]) / d_g ([M][C]).
// EPI 1: A=d_yh, B=d_wout_h, writes out rows.
template<int EPI, int KBASE>
__global__ __launch_bounds__(256) void gemm_mma(
    const float* __restrict__ bias0, const float* __restrict__ bias1,
    float* __restrict__ outp)
{
    extern __shared__ char smem[];
    uint32_t sb = smem_u32(smem);
    const int t   = threadIdx.x;
    const int wid = t >> 5, lid = t & 31;
    const int NKC = KBASE / 64;

    int sel, n0;
    const __half* Aglob;
    const __half* B;
    const float* bias;
    if (EPI == 0) {
        Aglob = d_xh;
        sel = (blockIdx.x >= DI / 128);
        n0  = (blockIdx.x & (DI / 128 - 1)) * 128;
        B = sel ? d_wg_h : d_win_h;
        bias = sel ? bias1 : bias0;
    } else {
        Aglob = d_yh;
        sel = 0;
        n0  = blockIdx.x * 128;
        B = d_wout_h;
        bias = bias0;
    }
    const int m0 = blockIdx.y * 128;
    const char* Abase = (const char*)(Aglob + (size_t)m0 * KBASE);
    const char* Bbase = (const char*)(B + (size_t)n0 * KBASE);

#pragma unroll
    for (int p = 0; p < NSTAGE - 1; p++) {
        load_stage<KBASE>(sb, p, Abase + p * 128, Bbase + p * 128);
        CP_COMMIT();
    }

    const int wm = (wid & 1) * 64;
    const int wn = (wid >> 1) * 32;

    float acc[4][4][4];
#pragma unroll
    for (int i = 0; i < 4; i++)
#pragma unroll
        for (int j = 0; j < 4; j++)
#pragma unroll
            for (int q = 0; q < 4; q++) acc[i][j][q] = 0.f;

    for (int i = 0; i < NKC; i++) {
        cp_wait<NSTAGE - 2>();
        __syncthreads();
        int j = i + NSTAGE - 1;
        if (j < NKC) {
            load_stage<KBASE>(sb, j & (NSTAGE - 1), Abase + j * 128,
                              Bbase + j * 128);
        }
        CP_COMMIT();

        uint32_t sA = sb + (i & (NSTAGE - 1)) * STAGE_B;
        uint32_t sB = sA + 16384;
#pragma unroll
        for (int kk = 0; kk < 4; kk++) {
            uint32_t a[4][4], b[2][4];
#pragma unroll
            for (int mi = 0; mi < 4; mi++) {
                int row = wm + mi * 16 + (lid & 15);
                int ch  = kk * 2 + (lid >> 4);
                ldmx4(a[mi], sA + row * BKB + ((ch ^ (row & 7)) << 4));
            }
#pragma unroll
            for (int bi = 0; bi < 2; bi++) {
                int row = wn + bi * 16 + (lid & 15);
                int ch  = kk * 2 + (lid >> 4);
                ldmx4(b[bi], sB + row * BKB + ((ch ^ (row & 7)) << 4));
            }
#pragma unroll
            for (int mi = 0; mi < 4; mi++) {
#pragma unroll
                for (int bi = 0; bi < 2; bi++) {
                    mma16816(acc[mi][bi * 2 + 0], a[mi], b[bi][0], b[bi][2]);
                    mma16816(acc[mi][bi * 2 + 1], a[mi], b[bi][1], b[bi][3]);
                }
            }
        }
        __syncthreads();
    }

    // ---- epilogue ----
    const int bidx = m0 >> 12;
    const int q4   = lid & 3;
    const int r8   = lid >> 2;

    if (EPI == 0) {
        if (sel) {
            // gate: sigmoid, store m-major [M][DI]
#pragma unroll
            for (int mi = 0; mi < 4; mi++) {
#pragma unroll
                for (int ni = 0; ni < 4; ni++) {
                    int n = n0 + wn + ni * 8 + 2 * q4;
                    float bz0 = bias[n], bz1 = bias[n + 1];
#pragma unroll
                    for (int rr = 0; rr < 2; rr++) {
                        int m = m0 + wm + mi * 16 + r8 + rr * 8;
                        float2 v;
                        v.x = 1.f / (1.f + __expf(-(acc[mi][ni][rr*2+0] + bz0)));
                        v.y = 1.f / (1.f + __expf(-(acc[mi][ni][rr*2+1] + bz1)));
                        *(float2*)(d_g + (size_t)m * DI + n) = v;
                    }
                }
            }
        } else {
            // xp: store transposed [C][S]
            float* dp = d_xp + (size_t)bidx * DI * SEQ;
#pragma unroll
            for (int mi = 0; mi < 4; mi++) {
#pragma unroll
                for (int ni = 0; ni < 4; ni++) {
                    int n = n0 + wn + ni * 8 + 2 * q4;
                    float bz0 = bias[n], bz1 = bias[n + 1];
#pragma unroll
                    for (int rr = 0; rr < 2; rr++) {
                        int m = m0 + wm + mi * 16 + r8 + rr * 8;
                        int s = m & (SEQ - 1);
                        dp[(size_t)n * SEQ + s]       = acc[mi][ni][rr*2+0] + bz0;
                        dp[(size_t)(n + 1) * SEQ + s] = acc[mi][ni][rr*2+1] + bz1;
                    }
                }
            }
        }
    } else {
#pragma unroll
        for (int mi = 0; mi < 4; mi++) {
#pragma unroll
            for (int ni = 0; ni < 4; ni++) {
                int n = n0 + wn + ni * 8 + 2 * q4;
                float bz0 = bias[n], bz1 = bias[n + 1];
#pragma unroll
                for (int rr = 0; rr < 2; rr++) {
                    int m = m0 + wm + mi * 16 + r8 + rr * 8;
                    float2 v;
                    v.x = acc[mi][ni][rr * 2 + 0] + bz0;
                    v.y = acc[mi][ni][rr * 2 + 1] + bz1;
                    *(float2*)(outp + (size_t)m * DM + n) = v;
                }
            }
        }
    }
}

// ---------------------------------------------------------------- launch
extern "C" void kernel_launch(void* const* d_in, const int* in_sizes, int n_in,
                              void* d_out, int out_size)
{
    const float* x      = (const float*)d_in[0];
    const float* w_in   = (const float*)d_in[1];
    const float* b_in   = (const float*)d_in[2];
    const float* w_gate = (const float*)d_in[3];
    const float* b_gate = (const float*)d_in[4];
    const float* A      = (const float*)d_in[5];
    const float* B_ssm  = (const float*)d_in[6];
    const float* C_ssm  = (const float*)d_in[7];
    const float* w_out  = (const float*)d_in[8];
    const float* b_out  = (const float*)d_in[9];
    float* out = (float*)d_out;

    static bool attr_done = false;
    if (!attr_done) {
        cudaFuncSetAttribute(gemm_mma<0, DM>,
                             cudaFuncAttributeMaxDynamicSharedMemorySize, SMEM_GEMM);
        cudaFuncSetAttribute(gemm_mma<1, DI>,
                             cudaFuncAttributeMaxDynamicSharedMemorySize, SMEM_GEMM);
        attr_done = true;
    }

    taps_kernel<<<DI / 256, 256>>>(A, B_ssm, C_ssm);
    conv_x_kernel<<<(BATCH * SEQ * DM / 4) / 256, 256>>>(x);
    conv_w_kernel<0, DM, DI><<<dim3(DI / 32, DM / 32), dim3(32, 8)>>>(w_in);
    conv_w_kernel<1, DM, DI><<<dim3(DI / 32, DM / 32), dim3(32, 8)>>>(w_gate);
    conv_w_kernel<2, DI, DM><<<dim3(DM / 32, DI / 32), dim3(32, 8)>>>(w_out);

    gemm_mma<0, DM><<<dim3(2 * DI / 128, BATCH * SEQ / 128), 256, SMEM_GEMM>>>(
        b_in, b_gate, nullptr);

    fir_kernel<<<dim3(SEQ / 256, DI / 32, BATCH), 256>>>();

    gemm_mma<1, DI><<<dim3(DM / 128, BATCH * SEQ / 128), 256, SMEM_GEMM>>>(
        b_out, nullptr, out);
}

// round 7
// speedup vs baseline: 5.1461x; 1.2109x over previous
#include <cuda_runtime.h>
#include <cuda_fp16.h>
#include <cstdint>

// ---------------------------------------------------------------- constants
#define BATCH 4
#define SEQ   4096
#define DM    1024
#define DI    2048
#define DS    16
#define NTAPS 32

// ---------------------------------------------------------------- scratch (device globals)
__device__ float  d_taps[DI*NTAPS];
__device__ __half d_xh   [(size_t)BATCH*SEQ*DM];   // input act fp16 [B*S][DM]
__device__ __half d_xp16 [(size_t)BATCH*SEQ*DI];   // in-proj fp16 [B*S][DI]
__device__ __half d_g16  [(size_t)BATCH*SEQ*DI];   // gate fp16 [B*S][DI]
__device__ __half d_yh   [(size_t)BATCH*SEQ*DI];   // fir*gate fp16 [B*S][DI]
__device__ __half d_win_h [(size_t)DI*DM];         // [N][K]
__device__ __half d_wg_h  [(size_t)DI*DM];
__device__ __half d_wout_h[(size_t)DM*DI];         // [N][K]

// ---------------------------------------------------------------- utils
__device__ __forceinline__ uint32_t smem_u32(const void* p) {
    uint32_t a;
    asm("{ .reg .u64 t; cvta.to.shared.u64 t, %1; cvt.u32.u64 %0, t; }"
        : "=r"(a) : "l"(p));
    return a;
}
__device__ __forceinline__ void cpa16(uint32_t dst, const void* src) {
    asm volatile("cp.async.cg.shared.global [%0], [%1], 16;"
                 :: "r"(dst), "l"(src) : "memory");
}
#define CP_COMMIT() asm volatile("cp.async.commit_group;" ::: "memory")
template<int N> __device__ __forceinline__ void cp_wait() {
    asm volatile("cp.async.wait_group %0;" :: "n"(N) : "memory");
}
__device__ __forceinline__ void ldmx4(uint32_t* r, uint32_t addr) {
    asm volatile("ldmatrix.sync.aligned.m8n8.x4.shared.b16 {%0,%1,%2,%3}, [%4];"
                 : "=r"(r[0]), "=r"(r[1]), "=r"(r[2]), "=r"(r[3]) : "r"(addr));
}
__device__ __forceinline__ void mma16816(float* c, const uint32_t* a,
                                         uint32_t b0, uint32_t b1) {
    asm volatile(
        "mma.sync.aligned.m16n8k16.row.col.f32.f16.f16.f32 "
        "{%0,%1,%2,%3}, {%4,%5,%6,%7}, {%8,%9}, {%0,%1,%2,%3};"
        : "+f"(c[0]), "+f"(c[1]), "+f"(c[2]), "+f"(c[3])
        : "r"(a[0]), "r"(a[1]), "r"(a[2]), "r"(a[3]), "r"(b0), "r"(b1));
}

// ---------------------------------------------------------------- taps
__global__ __launch_bounds__(256) void taps_kernel(
    const float* __restrict__ A, const float* __restrict__ B_ssm,
    const float* __restrict__ C_ssm)
{
    int c = blockIdx.x * blockDim.x + threadIdx.x;
    if (c >= DI) return;
    const float* Ac = A + (size_t)c * DS * DS;
    float v[DS], Cv[DS];
#pragma unroll
    for (int n = 0; n < DS; n++) { v[n] = B_ssm[c*DS+n]; Cv[n] = C_ssm[c*DS+n]; }
    for (int j = 0; j < NTAPS; j++) {
        float y = 0.f;
#pragma unroll
        for (int n = 0; n < DS; n++) y = fmaf(Cv[n], v[n], y);
        d_taps[c*NTAPS + j] = y;
        float w[DS];
#pragma unroll
        for (int n = 0; n < DS; n++) {
            float acc = 0.f;
#pragma unroll
            for (int m = 0; m < DS; m++) acc = fmaf(Ac[n*DS+m], v[m], acc);
            w[n] = acc;
        }
#pragma unroll
        for (int n = 0; n < DS; n++) v[n] = w[n];
    }
}

// ---------------------------------------------------------------- x f32 -> fp16
__global__ __launch_bounds__(256) void conv_x_kernel(const float* __restrict__ x)
{
    size_t idx = (size_t)blockIdx.x * 256 + threadIdx.x;   // one float4
    float4 v = *(const float4*)(x + idx * 4);
    __half2 h0 = __floats2half2_rn(v.x, v.y);
    __half2 h1 = __floats2half2_rn(v.z, v.w);
    uint2 pk = { *(uint32_t*)&h0, *(uint32_t*)&h1 };
    *(uint2*)((__half*)d_xh + idx * 4) = pk;
}

// ---------------------------------------------------------------- W [K][N]f32 -> [N][K]fp16
template<int WHICH, int K, int N>
__global__ void conv_w_kernel(const float* __restrict__ W)
{
    __shared__ float tb[32][33];
    __half* WT = (WHICH == 0 ? d_win_h : WHICH == 1 ? d_wg_h : d_wout_h);
    int n0 = blockIdx.x * 32, k0 = blockIdx.y * 32;
    int tx = threadIdx.x, ty = threadIdx.y;
#pragma unroll
    for (int i = ty; i < 32; i += 8)
        tb[i][tx] = W[(size_t)(k0 + i) * N + n0 + tx];
    __syncthreads();
#pragma unroll
    for (int j = ty; j < 32; j += 8)
        WT[(size_t)(n0 + j) * K + k0 + tx] = __float2half_rn(tb[tx][j]);
}

// ---------------------------------------------------------------- FIR + gate (all fp16 I/O, m-major)
// Block: 32 channels x 256 s. Loads xp tile [s][c] coalesced, smem [z][c].
__global__ __launch_bounds__(256) void fir_kernel()
{
    __shared__ float sx[288][33];       // [32 halo + 256][c]
    __shared__ float st[32][33];        // taps[c][j]
    const int t = threadIdx.x;
    const int c0 = blockIdx.y * 32, b = blockIdx.z;
    const int s0 = blockIdx.x * 256;
    const size_t rowbase = (size_t)b * SEQ;

    // load xp tile: 288 rows x 32 c, fp16, coalesced (64B per row)
    for (int idx = t; idx < 288 * 32; idx += 256) {
        int z = idx >> 5, c = idx & 31;
        int s = s0 - 32 + z;
        float v = 0.f;
        if (s >= 0) v = __half2float(d_xp16[(rowbase + s) * DI + c0 + c]);
        sx[z][c] = v;
    }
    for (int idx = t; idx < 32 * 32; idx += 256) {
        int r = idx >> 5, j = idx & 31;
        st[r][j] = d_taps[(c0 + r) * NTAPS + j];
    }
    __syncthreads();

    const int c  = t & 31;
    const int sb = (t >> 5) * 32;       // warp-uniform s-base
    float k[NTAPS];
#pragma unroll
    for (int j = 0; j < NTAPS; j++) k[j] = st[c][j];

#pragma unroll
    for (int ch = 0; ch < 4; ch++) {
        const int sc = sb + ch * 8;
        float w[39];
#pragma unroll
        for (int z = 0; z < 39; z++) w[z] = sx[sc + 1 + z][c];
        float acc[8];
#pragma unroll
        for (int i = 0; i < 8; i++) acc[i] = 0.f;
#pragma unroll
        for (int j = 0; j < NTAPS; j++)
#pragma unroll
            for (int i = 0; i < 8; i++)
                acc[i] = fmaf(k[j], w[31 + i - j], acc[i]);
#pragma unroll
        for (int i = 0; i < 8; i++) {
            size_t row = rowbase + s0 + sc + i;
            float gv = __half2float(d_g16[row * DI + c0 + c]);
            d_yh[row * DI + c0 + c] = __float2half_rn(acc[i] * gv);
        }
    }
}

// ---------------------------------------------------------------- mma.sync GEMM (fp16)
// C[128x128] per CTA. A [M][K] fp16, B [N][K] fp16.
// BK=64 (128B rows, XOR-8 swizzle), 3-stage cp.async, 8 warps 64x32 tiles, 2 CTA/SM.
#define BKB        128                    // bytes per smem row (64 fp16)
#define STAGE_B    32768                  // 16KB A + 16KB B
#define NSTAGE     3
#define SMEM_GEMM  (NSTAGE * STAGE_B)

template<int KBASE>
__device__ __forceinline__ void load_stage(uint32_t sb, int slot,
                                           const char* Ac, const char* Bc)
{
    const int ld = KBASE * 2;             // row stride bytes
    uint32_t sA = sb + slot * STAGE_B;
    uint32_t sB = sA + 16384;
    const int t = threadIdx.x;
#pragma unroll
    for (int it = 0; it < 4; it++) {
        int idx = t + it * 256;
        int r = idx >> 3, c = idx & 7;
        cpa16(sA + r * BKB + ((c ^ (r & 7)) << 4), Ac + (size_t)r * ld + c * 16);
    }
#pragma unroll
    for (int it = 0; it < 4; it++) {
        int idx = t + it * 256;
        int r = idx >> 3, c = idx & 7;
        cpa16(sB + r * BKB + ((c ^ (r & 7)) << 4), Bc + (size_t)r * ld + c * 16);
    }
}

// EPI 0: A=d_xh, B=d_win_h/d_wg_h (dual), writes d_xp16 / d_g16 (m-major fp16).
// EPI 1: A=d_yh, B=d_wout_h, writes f32 out rows.
template<int EPI, int KBASE>
__global__ __launch_bounds__(256, 2) void gemm_mma(
    const float* __restrict__ bias0, const float* __restrict__ bias1,
    float* __restrict__ outp)
{
    extern __shared__ char smem[];
    uint32_t sb = smem_u32(smem);
    const int t   = threadIdx.x;
    const int wid = t >> 5, lid = t & 31;
    const int NKC = KBASE / 64;

    int sel, n0;
    const __half* Aglob;
    const __half* B;
    const float* bias;
    if (EPI == 0) {
        Aglob = d_xh;
        sel = (blockIdx.x >= DI / 128);
        n0  = (blockIdx.x & (DI / 128 - 1)) * 128;
        B = sel ? d_wg_h : d_win_h;
        bias = sel ? bias1 : bias0;
    } else {
        Aglob = d_yh;
        sel = 0;
        n0  = blockIdx.x * 128;
        B = d_wout_h;
        bias = bias0;
    }
    const int m0 = blockIdx.y * 128;
    const char* Abase = (const char*)(Aglob + (size_t)m0 * KBASE);
    const char* Bbase = (const char*)(B + (size_t)n0 * KBASE);

#pragma unroll
    for (int p = 0; p < NSTAGE - 1; p++) {
        load_stage<KBASE>(sb, p, Abase + p * 128, Bbase + p * 128);
        CP_COMMIT();
    }

    const int wm = (wid & 1) * 64;
    const int wn = (wid >> 1) * 32;

    float acc[4][4][4];
#pragma unroll
    for (int i = 0; i < 4; i++)
#pragma unroll
        for (int j = 0; j < 4; j++)
#pragma unroll
            for (int q = 0; q < 4; q++) acc[i][j][q] = 0.f;

    int slot = 0, slot_ld = NSTAGE - 1;
    for (int i = 0; i < NKC; i++) {
        cp_wait<NSTAGE - 2>();
        __syncthreads();
        int j = i + NSTAGE - 1;
        if (j < NKC) {
            load_stage<KBASE>(sb, slot_ld, Abase + j * 128, Bbase + j * 128);
        }
        CP_COMMIT();
        if (++slot_ld == NSTAGE) slot_ld = 0;

        uint32_t sA = sb + slot * STAGE_B;
        uint32_t sB = sA + 16384;
        if (++slot == NSTAGE) slot = 0;
#pragma unroll
        for (int kk = 0; kk < 4; kk++) {
            uint32_t a[4][4], b[2][4];
#pragma unroll
            for (int mi = 0; mi < 4; mi++) {
                int row = wm + mi * 16 + (lid & 15);
                int ch  = kk * 2 + (lid >> 4);
                ldmx4(a[mi], sA + row * BKB + ((ch ^ (row & 7)) << 4));
            }
#pragma unroll
            for (int bi = 0; bi < 2; bi++) {
                int row = wn + bi * 16 + (lid & 15);
                int ch  = kk * 2 + (lid >> 4);
                ldmx4(b[bi], sB + row * BKB + ((ch ^ (row & 7)) << 4));
            }
#pragma unroll
            for (int mi = 0; mi < 4; mi++) {
#pragma unroll
                for (int bi = 0; bi < 2; bi++) {
                    mma16816(acc[mi][bi * 2 + 0], a[mi], b[bi][0], b[bi][2]);
                    mma16816(acc[mi][bi * 2 + 1], a[mi], b[bi][1], b[bi][3]);
                }
            }
        }
        __syncthreads();
    }

    // ---- epilogue ----
    const int q4 = lid & 3;
    const int r8 = lid >> 2;

    if (EPI == 0) {
        __half* dst = sel ? d_g16 : d_xp16;
#pragma unroll
        for (int mi = 0; mi < 4; mi++) {
#pragma unroll
            for (int ni = 0; ni < 4; ni++) {
                int n = n0 + wn + ni * 8 + 2 * q4;
                float bz0 = bias[n], bz1 = bias[n + 1];
#pragma unroll
                for (int rr = 0; rr < 2; rr++) {
                    int m = m0 + wm + mi * 16 + r8 + rr * 8;
                    float v0 = acc[mi][ni][rr * 2 + 0] + bz0;
                    float v1 = acc[mi][ni][rr * 2 + 1] + bz1;
                    if (sel) {
                        v0 = 1.f / (1.f + __expf(-v0));
                        v1 = 1.f / (1.f + __expf(-v1));
                    }
                    __half2 h2 = __floats2half2_rn(v0, v1);
                    *(__half2*)(dst + (size_t)m * DI + n) = h2;
                }
            }
        }
    } else {
#pragma unroll
        for (int mi = 0; mi < 4; mi++) {
#pragma unroll
            for (int ni = 0; ni < 4; ni++) {
                int n = n0 + wn + ni * 8 + 2 * q4;
                float bz0 = bias[n], bz1 = bias[n + 1];
#pragma unroll
                for (int rr = 0; rr < 2; rr++) {
                    int m = m0 + wm + mi * 16 + r8 + rr * 8;
                    float2 v;
                    v.x = acc[mi][ni][rr * 2 + 0] + bz0;
                    v.y = acc[mi][ni][rr * 2 + 1] + bz1;
                    *(float2*)(outp + (size_t)m * DM + n) = v;
                }
            }
        }
    }
}

// ---------------------------------------------------------------- launch
extern "C" void kernel_launch(void* const* d_in, const int* in_sizes, int n_in,
                              void* d_out, int out_size)
{
    const float* x      = (const float*)d_in[0];
    const float* w_in   = (const float*)d_in[1];
    const float* b_in   = (const float*)d_in[2];
    const float* w_gate = (const float*)d_in[3];
    const float* b_gate = (const float*)d_in[4];
    const float* A      = (const float*)d_in[5];
    const float* B_ssm  = (const float*)d_in[6];
    const float* C_ssm  = (const float*)d_in[7];
    const float* w_out  = (const float*)d_in[8];
    const float* b_out  = (const float*)d_in[9];
    float* out = (float*)d_out;

    static bool attr_done = false;
    if (!attr_done) {
        cudaFuncSetAttribute(gemm_mma<0, DM>,
                             cudaFuncAttributeMaxDynamicSharedMemorySize, SMEM_GEMM);
        cudaFuncSetAttribute(gemm_mma<1, DI>,
                             cudaFuncAttributeMaxDynamicSharedMemorySize, SMEM_GEMM);
        attr_done = true;
    }

    taps_kernel<<<DI / 256, 256>>>(A, B_ssm, C_ssm);
    conv_x_kernel<<<(BATCH * SEQ * DM / 4) / 256, 256>>>(x);
    conv_w_kernel<0, DM, DI><<<dim3(DI / 32, DM / 32), dim3(32, 8)>>>(w_in);
    conv_w_kernel<1, DM, DI><<<dim3(DI / 32, DM / 32), dim3(32, 8)>>>(w_gate);
    conv_w_kernel<2, DI, DM><<<dim3(DM / 32, DI / 32), dim3(32, 8)>>>(w_out);

    gemm_mma<0, DM><<<dim3(2 * DI / 128, BATCH * SEQ / 128), 256, SMEM_GEMM>>>(
        b_in, b_gate, nullptr);

    fir_kernel<<<dim3(SEQ / 256, DI / 32, BATCH), 256>>>();

    gemm_mma<1, DI><<<dim3(DM / 128, BATCH * SEQ / 128), 256, SMEM_GEMM>>>(
        b_out, nullptr, out);
}